// round 1
// baseline (speedup 1.0000x reference)
#include <cuda_runtime.h>
#include <cstddef>

#define NN   20000
#define EE   320000
#define HH   8
#define FUNI 256
#define FOUT 64
#define HF   512   // H*FOUT

// ---------------- scratch (device globals; no runtime allocation) ----------------
__device__ float g_trans0[NN * FUNI];
__device__ float g_trans1[NN * FUNI];
__device__ float g_Bp[512 * HF];          // repacked GAT weight [fin, 512]
__device__ float g_hp[NN * HF];           // per-layer projected features [n][h][o]
__device__ float g_x0[NN * HF];           // layer-0 aggregated output (pre-ELU)
__device__ float g_o1a[NN * HF];          // layer-1 aggregated output, type 0
__device__ float g_o1b[NN * HF];          // layer-1 aggregated output, type 1
__device__ float g_s[NN * HH];
__device__ float g_t[NN * HH];
__device__ float g_denom[NN * HH];
__device__ float g_ex[EE * HH];
__device__ float g_fa[FOUT];

// ---------------- helpers ----------------
__device__ __forceinline__ float eluf(float x) {
    return x > 0.f ? x : (__expf(x) - 1.f);
}

__device__ __forceinline__ void red4(float* p, float4 v) {
    asm volatile("red.global.add.v4.f32 [%0], {%1,%2,%3,%4};"
                 :: "l"(p), "f"(v.x), "f"(v.y), "f"(v.z), "f"(v.w) : "memory");
}

// ---------------- tiled FP32 GEMM: C[M,NC] = A[M,K] @ B[K,NC] ----------------
// BM=BN=128, BK=8, 256 threads, 8x8 per-thread microtile. ELU applied to A load.
template<int ELU>
__global__ __launch_bounds__(256) void sgemm128(const float* __restrict__ A,
                                                const float* __restrict__ B,
                                                float* __restrict__ C,
                                                int M, int K, int NC)
{
    __shared__ float As[8][128];
    __shared__ float Bs[8][128];
    const int tid = threadIdx.x;
    const int bm = blockIdx.y << 7;
    const int bn = blockIdx.x << 7;
    const int tr = tid >> 4;       // 0..15
    const int tc = tid & 15;       // 0..15

    float acc[8][8];
#pragma unroll
    for (int i = 0; i < 8; i++)
#pragma unroll
        for (int j = 0; j < 8; j++) acc[i][j] = 0.f;

    const int arow = bm + (tid >> 1);
    const int ac4  = (tid & 1) << 2;
    const int brow = tid >> 5;            // 0..7
    const int bc4  = (tid & 31) << 2;     // 0..124

    const float* Aptr = A + (size_t)arow * K + ac4;
    const float* Bptr = B + (size_t)brow * NC + bn + bc4;

    for (int k0 = 0; k0 < K; k0 += 8) {
        float4 av = make_float4(0.f, 0.f, 0.f, 0.f);
        if (arow < M) av = *(const float4*)(Aptr + k0);
        if (ELU) {
            av.x = eluf(av.x); av.y = eluf(av.y);
            av.z = eluf(av.z); av.w = eluf(av.w);
        }
        As[ac4 + 0][tid >> 1] = av.x;
        As[ac4 + 1][tid >> 1] = av.y;
        As[ac4 + 2][tid >> 1] = av.z;
        As[ac4 + 3][tid >> 1] = av.w;

        float4 bv = *(const float4*)(Bptr + (size_t)k0 * NC);
        *(float4*)&Bs[brow][bc4] = bv;
        __syncthreads();

#pragma unroll
        for (int kk = 0; kk < 8; kk++) {
            float a[8], b[8];
            *(float4*)(a)     = *(const float4*)&As[kk][tr << 3];
            *(float4*)(a + 4) = *(const float4*)&As[kk][(tr << 3) + 4];
            *(float4*)(b)     = *(const float4*)&Bs[kk][tc << 3];
            *(float4*)(b + 4) = *(const float4*)&Bs[kk][(tc << 3) + 4];
#pragma unroll
            for (int i = 0; i < 8; i++)
#pragma unroll
                for (int j = 0; j < 8; j++)
                    acc[i][j] += a[i] * b[j];
        }
        __syncthreads();
    }

#pragma unroll
    for (int i = 0; i < 8; i++) {
        int row = bm + (tr << 3) + i;
        if (row < M) {
            float4* cp = (float4*)(C + (size_t)row * NC + bn + (tc << 3));
            cp[0] = make_float4(acc[i][0], acc[i][1], acc[i][2], acc[i][3]);
            cp[1] = make_float4(acc[i][4], acc[i][5], acc[i][6], acc[i][7]);
        }
    }
}

// repack w[H][fin][64] -> Bp[f*512 + h*64 + o]
__global__ void repack_w(const float* __restrict__ w, float* __restrict__ Bp, int fin)
{
    int i = blockIdx.x * blockDim.x + threadIdx.x;
    if (i >= fin * 512) return;
    int f = i >> 9;
    int c = i & 511;
    int h = c >> 6, o = c & 63;
    Bp[i] = w[(((size_t)h * fin + f) << 6) + o];
}

// s[n,h] = hp[n,h,:]·asrc[h,:],  t[n,h] = hp[n,h,:]·atrg[h,:]
__global__ void st_kernel(const float* __restrict__ hp,
                          const float* __restrict__ asrc,
                          const float* __restrict__ atrg)
{
    int idx = blockIdx.x * blockDim.x + threadIdx.x;
    if (idx >= NN * HH) return;
    int h = idx & 7;
    const float4* v = (const float4*)(hp + (size_t)idx * 64);
    const float4* a = (const float4*)(asrc + h * 64);
    const float4* b = (const float4*)(atrg + h * 64);
    float s = 0.f, t = 0.f;
#pragma unroll
    for (int k = 0; k < 16; k++) {
        float4 x = v[k], aa = a[k], bb = b[k];
        s += x.x * aa.x + x.y * aa.y + x.z * aa.z + x.w * aa.w;
        t += x.x * bb.x + x.y * bb.y + x.z * bb.z + x.w * bb.w;
    }
    g_s[idx] = s;
    g_t[idx] = t;
}

// zero denom + selected aggregation buffer
__global__ void zero_agg(int sel)
{
    float* p = (sel == 0) ? g_x0 : ((sel == 1) ? g_o1a : g_o1b);
    int i = blockIdx.x * blockDim.x + threadIdx.x;
    if (i < NN * HF / 4) ((float4*)p)[i] = make_float4(0.f, 0.f, 0.f, 0.f);
    if (i < NN * HH) g_denom[i] = 0.f;
}

__device__ __forceinline__ float lre(float v) {
    // leaky_relu(0.2) then exp; global max-shift in the reference cancels in alpha.
    return __expf(fmaxf(v, 0.2f * v));
}

// per-edge: ex = exp(leaky_relu(s[src]+t[trg])); accumulate denom per (trg,h)
__global__ void edge_attn(const int* __restrict__ src, const int* __restrict__ trg)
{
    int e = blockIdx.x * blockDim.x + threadIdx.x;
    if (e >= EE) return;
    int si = src[e], ti = trg[e];
    float4 s0 = *(const float4*)(g_s + si * 8);
    float4 s1 = *(const float4*)(g_s + si * 8 + 4);
    float4 t0 = *(const float4*)(g_t + ti * 8);
    float4 t1 = *(const float4*)(g_t + ti * 8 + 4);
    float4 e0, e1;
    e0.x = lre(s0.x + t0.x); e0.y = lre(s0.y + t0.y);
    e0.z = lre(s0.z + t0.z); e0.w = lre(s0.w + t0.w);
    e1.x = lre(s1.x + t1.x); e1.y = lre(s1.y + t1.y);
    e1.z = lre(s1.z + t1.z); e1.w = lre(s1.w + t1.w);
    *(float4*)(g_ex + (size_t)e * 8)     = e0;
    *(float4*)(g_ex + (size_t)e * 8 + 4) = e1;
    red4(g_denom + ti * 8, e0);
    red4(g_denom + ti * 8 + 4, e1);
}

// warp per edge: out[trg] += hp[src] * alpha  (512 floats, vector reductions)
__global__ __launch_bounds__(256) void scatter(const int* __restrict__ src,
                                               const int* __restrict__ trg,
                                               const float* __restrict__ hp,
                                               float* __restrict__ out)
{
    int w = (blockIdx.x * 256 + threadIdx.x) >> 5;
    int lane = threadIdx.x & 31;
    if (w >= EE) return;
    int si = src[w], ti = trg[w];
    float alpha = 0.f;
    if (lane < 8)
        alpha = g_ex[(size_t)w * 8 + lane] / (g_denom[ti * 8 + lane] + 1e-16f);
    const float4* hv = (const float4*)(hp + (size_t)si * 512);
    float* ob = out + (size_t)ti * 512;
#pragma unroll
    for (int j = 0; j < 4; j++) {
        int c = lane + 32 * j;          // float4 chunk index 0..127
        float al = __shfl_sync(0xffffffffu, alpha, c >> 4);   // h = c/16
        float4 v = hv[c];
        v.x *= al; v.y *= al; v.z *= al; v.w *= al;
        red4(ob + (c << 2), v);
    }
}

// fa[o] = trans1[0,:] @ aw1[:,o]
__global__ void fa_kernel(const float* __restrict__ trans1, const float* __restrict__ aw1)
{
    int o = threadIdx.x;
    float acc = 0.f;
    for (int f = 0; f < FUNI; f++) acc += trans1[f] * aw1[f * 64 + o];
    g_fa[o] = acc;
}

// per node: head-mean, attention fusion over 2 types, FC, log_softmax
__global__ __launch_bounds__(64) void final_kernel(const float* __restrict__ aw2,
                                                   const float* __restrict__ am,
                                                   const float* __restrict__ fcw,
                                                   const float* __restrict__ fcb,
                                                   float* __restrict__ out)
{
    __shared__ float ta[2][64];
    __shared__ float r0[64], r1[64];
    __shared__ float sc[2];
    int n = blockIdx.x, o = threadIdx.x;

    float m0 = 0.f, m1 = 0.f;
    const float* p0 = g_o1a + (size_t)n * 512 + o;
    const float* p1 = g_o1b + (size_t)n * 512 + o;
#pragma unroll
    for (int h = 0; h < 8; h++) { m0 += p0[h * 64]; m1 += p1[h * 64]; }
    m0 *= 0.125f; m1 *= 0.125f;
    ta[0][o] = m0; ta[1][o] = m1;
    __syncthreads();

    float amo = am[o];
    float fa = g_fa[o];
    {
        float acc0 = fa, acc1 = fa;
        for (int d = 0; d < 64; d++) {
            float w = aw2[d * 64 + o];
            acc0 += ta[0][d] * w;
            acc1 += ta[1][d] * w;
        }
        r0[o] = tanhf(acc0) * amo;
        r1[o] = tanhf(acc1) * amo;
    }
    __syncthreads();
    if (o == 0) {
        float s0 = 0.f, s1 = 0.f;
        for (int d = 0; d < 64; d++) { s0 += r0[d]; s1 += r1[d]; }
        sc[0] = s0; sc[1] = s1;
    }
    __syncthreads();
    float mx = fmaxf(sc[0], sc[1]);
    float b0 = __expf(sc[0] - mx), b1 = __expf(sc[1] - mx);
    float inv = 1.f / (b0 + b1);
    b0 *= inv; b1 *= inv;
    float fus = b0 * m0 + b1 * m1;

    r0[o] = m0 * fcw[o * 2 + 0] + m1 * fcw[(64 + o) * 2 + 0] + fus * fcw[(128 + o) * 2 + 0];
    r1[o] = m0 * fcw[o * 2 + 1] + m1 * fcw[(64 + o) * 2 + 1] + fus * fcw[(128 + o) * 2 + 1];
    __syncthreads();
    if (o == 0) {
        float l0 = fcb[0], l1 = fcb[1];
        for (int d = 0; d < 64; d++) { l0 += r0[d]; l1 += r1[d]; }
        float m = fmaxf(l0, l1);
        float lse = m + logf(__expf(l0 - m) + __expf(l1 - m));
        out[n * 2 + 0] = l0 - lse;
        out[n * 2 + 1] = l1 - lse;
    }
}

// ---------------- launcher ----------------
extern "C" void kernel_launch(void* const* d_in, const int* in_sizes, int n_in,
                              void* d_out, int out_size)
{
    const float* hemb0 = (const float*)d_in[0];
    const float* hemb1 = (const float*)d_in[1];
    const float* W0    = (const float*)d_in[2];
    const float* W1    = (const float*)d_in[3];
    const float* gw[2][2]    = {{(const float*)d_in[4],  (const float*)d_in[7]},
                                {(const float*)d_in[10], (const float*)d_in[13]}};
    const float* gasrc[2][2] = {{(const float*)d_in[5],  (const float*)d_in[8]},
                                {(const float*)d_in[11], (const float*)d_in[14]}};
    const float* gatrg[2][2] = {{(const float*)d_in[6],  (const float*)d_in[9]},
                                {(const float*)d_in[12], (const float*)d_in[15]}};
    const float* aw1 = (const float*)d_in[16];
    const float* aw2 = (const float*)d_in[17];
    const float* am  = (const float*)d_in[18];
    const float* fcw = (const float*)d_in[19];
    const float* fcb = (const float*)d_in[20];
    const int* edge[2] = {(const int*)d_in[21], (const int*)d_in[22]};

    float *trans[2], *Bp, *hp, *x0, *o1[2];
    cudaGetSymbolAddress((void**)&trans[0], g_trans0);
    cudaGetSymbolAddress((void**)&trans[1], g_trans1);
    cudaGetSymbolAddress((void**)&Bp,  g_Bp);
    cudaGetSymbolAddress((void**)&hp,  g_hp);
    cudaGetSymbolAddress((void**)&x0,  g_x0);
    cudaGetSymbolAddress((void**)&o1[0], g_o1a);
    cudaGetSymbolAddress((void**)&o1[1], g_o1b);

    const dim3 gemmT(FUNI / 128, (NN + 127) / 128);
    const dim3 gemmH(HF / 128, (NN + 127) / 128);

    sgemm128<0><<<gemmT, 256>>>(hemb0, W0, trans[0], NN, 128, FUNI);
    sgemm128<0><<<gemmT, 256>>>(hemb1, W1, trans[1], NN, 128, FUNI);

    for (int t = 0; t < 2; t++) {
        const int* src = edge[t];
        const int* trg = edge[t] + EE;

        // ---- layer 0 (fin = 256) ----
        repack_w<<<(FUNI * 512 + 255) / 256, 256>>>(gw[t][0], Bp, FUNI);
        sgemm128<0><<<gemmH, 256>>>(trans[t], Bp, hp, NN, FUNI, HF);
        st_kernel<<<(NN * HH + 255) / 256, 256>>>(hp, gasrc[t][0], gatrg[t][0]);
        zero_agg<<<(NN * HF / 4 + 255) / 256, 256>>>(0);
        edge_attn<<<(EE + 255) / 256, 256>>>(src, trg);
        scatter<<<(EE + 7) / 8, 256>>>(src, trg, hp, x0);

        // ---- layer 1 (fin = 512, ELU fused into A load) ----
        repack_w<<<(HF * 512 + 255) / 256, 256>>>(gw[t][1], Bp, HF);
        sgemm128<1><<<gemmH, 256>>>(x0, Bp, hp, NN, HF, HF);
        st_kernel<<<(NN * HH + 255) / 256, 256>>>(hp, gasrc[t][1], gatrg[t][1]);
        zero_agg<<<(NN * HF / 4 + 255) / 256, 256>>>(1 + t);
        edge_attn<<<(EE + 255) / 256, 256>>>(src, trg);
        scatter<<<(EE + 7) / 8, 256>>>(src, trg, hp, o1[t]);
    }

    fa_kernel<<<1, 64>>>(trans[1], aw1);
    final_kernel<<<NN, 64>>>(aw2, am, fcw, fcb, (float*)d_out);
}

// round 6
// speedup vs baseline: 1.6129x; 1.6129x over previous
#include <cuda_runtime.h>
#include <cstdint>
#include <cstddef>

#define NN   20000
#define EE   320000
#define HH   8
#define FUNI 256
#define FOUT 64
#define HF   512   // H*FOUT

// ---------------- scratch (device globals; no runtime allocation) ----------------
__device__ float g_trans0[NN * FUNI];
__device__ float g_trans1[NN * FUNI];
__device__ float g_Bp[512 * 512];         // repacked GAT weight, [N][K] K-major, tf32-rounded
__device__ float g_hp[NN * HF];           // projected features; also temp for rounded hemb1
__device__ float g_x0[NN * HF];           // layer-0 aggregated output
__device__ float g_o1a[NN * HF];          // layer-1 aggregated output, type 0
__device__ float g_o1b[NN * HF];          // layer-1 aggregated output, type 1
__device__ float g_s[NN * HH];
__device__ float g_t[NN * HH];
__device__ float g_denom[NN * HH];
__device__ float g_ex[EE * HH];           // also temp for rounded hemb0
__device__ float g_fa[FOUT];

// ---------------- helpers ----------------
__device__ __forceinline__ uint32_t smem_to_u32(const void* p) {
    uint32_t a;
    asm("{ .reg .u64 t; cvta.to.shared.u64 t, %1; cvt.u32.u64 %0, t; }" : "=r"(a) : "l"(p));
    return a;
}
__device__ __forceinline__ void cp16(uint32_t saddr, const void* g) {
    asm volatile("cp.async.cg.shared.global [%0], [%1], 16;" :: "r"(saddr), "l"(g));
}
__device__ __forceinline__ void sts_zero16(uint32_t saddr) {
    asm volatile("st.shared.v4.b32 [%0], {%1,%1,%1,%1};" :: "r"(saddr), "r"(0u));
}
#define CP_COMMIT() asm volatile("cp.async.commit_group;" ::: "memory")
#define CP_WAIT2()  asm volatile("cp.async.wait_group 2;" ::: "memory")

__device__ __forceinline__ float rna_tf32(float x) {
    uint32_t u; asm("cvt.rna.tf32.f32 %0, %1;" : "=r"(u) : "f"(x));
    return __uint_as_float(u);
}
__device__ __forceinline__ float eluf(float x) { return x > 0.f ? x : (__expf(x) - 1.f); }
__device__ __forceinline__ void red4(float* p, float4 v) {
    asm volatile("red.global.add.v4.f32 [%0], {%1,%2,%3,%4};"
                 :: "l"(p), "f"(v.x), "f"(v.y), "f"(v.z), "f"(v.w) : "memory");
}
__device__ __forceinline__ void mma_tf32(float* c, const uint32_t* a, const uint32_t* b) {
    asm volatile("mma.sync.aligned.m16n8k8.row.col.f32.tf32.tf32.f32 "
                 "{%0,%1,%2,%3}, {%4,%5,%6,%7}, {%8,%9}, {%0,%1,%2,%3};"
                 : "+f"(c[0]), "+f"(c[1]), "+f"(c[2]), "+f"(c[3])
                 : "r"(a[0]), "r"(a[1]), "r"(a[2]), "r"(a[3]), "r"(b[0]), "r"(b[1]));
}

// ---------------- mma.sync tf32 GEMM: C[M,NC] = A[M,K] @ Bt[NC,K]^T ----------------
// Block tile 128x128, 8 warps (4x2), warp tile 32x64 (2x8 m16n8k8 atoms).
// 3-stage cp.async pipeline, K-chunks of 16, SMEM row stride 20 floats (conflict-free).
#define KC      16
#define STAGES  3
#define STRIDEF 20
#define TILEF   (128 * STRIDEF)            // floats per tile (A or B)
#define STAGEF  (2 * TILEF)                // floats per stage
#define SMEM_GEMM (STAGES * STAGEF * 4)    // bytes = 61440

__global__ __launch_bounds__(256, 2)
void gemm_mma(const float* __restrict__ A, const float* __restrict__ Bt,
              float* __restrict__ C, int M, int K, int NC, int round_out)
{
    extern __shared__ float sm[];
    const int tid  = threadIdx.x;
    const int wid  = tid >> 5, lane = tid & 31;
    const int g    = lane >> 2, t = lane & 3;
    const int bm   = blockIdx.y << 7, bn = blockIdx.x << 7;
    const int m0   = (wid >> 1) * 32;       // warp row offset
    const int n0   = (wid & 1) * 64;        // warp col offset
    const int P    = K >> 4;                // K chunks of 16

    const uint32_t sb = smem_to_u32(sm);

    // per-thread load slots: 2 float4 per tile per stage
    const int lrow = tid >> 2;              // 0..63 (+64 for j=1)
    const int lc4  = tid & 3;

    float acc[2][8][4];
#pragma unroll
    for (int i = 0; i < 2; i++)
#pragma unroll
        for (int j = 0; j < 8; j++)
#pragma unroll
            for (int q = 0; q < 4; q++) acc[i][j][q] = 0.f;

    // ---- prefetch first STAGES chunks ----
#pragma unroll
    for (int s = 0; s < STAGES; s++) {
        uint32_t stb = sb + s * STAGEF * 4;
#pragma unroll
        for (int j = 0; j < 2; j++) {
            int row = lrow + j * 64;
            uint32_t sa = stb + (row * STRIDEF + lc4 * 4) * 4;
            int ar = bm + row;
            if (ar < M) cp16(sa, A + (size_t)ar * K + s * KC + lc4 * 4);
            else        sts_zero16(sa);
            uint32_t sbB = stb + TILEF * 4 + (row * STRIDEF + lc4 * 4) * 4;
            cp16(sbB, Bt + (size_t)(bn + row) * K + s * KC + lc4 * 4);
        }
        CP_COMMIT();
    }

    for (int p = 0; p < P; p++) {
        const int slot = p % STAGES;
        CP_WAIT2();
        __syncthreads();
        const float* As = sm + slot * STAGEF;
        const float* Bs = As + TILEF;

#pragma unroll
        for (int ks = 0; ks < 2; ks++) {
            uint32_t a[2][4], b[8][2];
#pragma unroll
            for (int i = 0; i < 2; i++) {
                const float* ab = As + (m0 + i * 16 + g) * STRIDEF + ks * 8 + t;
                a[i][0] = __float_as_uint(ab[0]);
                a[i][1] = __float_as_uint(ab[8 * STRIDEF]);
                a[i][2] = __float_as_uint(ab[4]);
                a[i][3] = __float_as_uint(ab[8 * STRIDEF + 4]);
            }
#pragma unroll
            for (int j = 0; j < 8; j++) {
                const float* bb = Bs + (n0 + j * 8 + g) * STRIDEF + ks * 8 + t;
                b[j][0] = __float_as_uint(bb[0]);
                b[j][1] = __float_as_uint(bb[4]);
            }
#pragma unroll
            for (int i = 0; i < 2; i++)
#pragma unroll
                for (int j = 0; j < 8; j++)
                    mma_tf32(acc[i][j], a[i], b[j]);
        }
        __syncthreads();

        int np = p + STAGES;
        if (np < P) {
            uint32_t stb = sb + slot * STAGEF * 4;
#pragma unroll
            for (int j = 0; j < 2; j++) {
                int row = lrow + j * 64;
                uint32_t sa = stb + (row * STRIDEF + lc4 * 4) * 4;
                int ar = bm + row;
                if (ar < M) cp16(sa, A + (size_t)ar * K + np * KC + lc4 * 4);
                else        sts_zero16(sa);
                uint32_t sbB = stb + TILEF * 4 + (row * STRIDEF + lc4 * 4) * 4;
                cp16(sbB, Bt + (size_t)(bn + row) * K + np * KC + lc4 * 4);
            }
        }
        CP_COMMIT();   // empty groups at tail keep wait_group accounting uniform
    }

    // ---- epilogue ----
#pragma unroll
    for (int i = 0; i < 2; i++) {
        int r0 = bm + m0 + i * 16 + g;
#pragma unroll
        for (int j = 0; j < 8; j++) {
            int col = bn + n0 + j * 8 + 2 * t;
            float c0 = acc[i][j][0], c1 = acc[i][j][1];
            float c2 = acc[i][j][2], c3 = acc[i][j][3];
            if (round_out) {
                c0 = rna_tf32(c0); c1 = rna_tf32(c1);
                c2 = rna_tf32(c2); c3 = rna_tf32(c3);
            }
            if (r0 < M)
                *(float2*)(C + (size_t)r0 * NC + col) = make_float2(c0, c1);
            if (r0 + 8 < M)
                *(float2*)(C + (size_t)(r0 + 8) * NC + col) = make_float2(c2, c3);
        }
    }
}

// ---------------- small prep kernels ----------------
__global__ void round_tf32_k(float* __restrict__ dst, const float* __restrict__ src, int n) {
    int i = blockIdx.x * blockDim.x + threadIdx.x;
    if (i < n) dst[i] = rna_tf32(src[i]);
}
// Wt[n*128 + k] = rna(W[k*256 + n]),  W is [128,256]
__global__ void transpose_round(float* __restrict__ Wt, const float* __restrict__ W) {
    int i = blockIdx.x * blockDim.x + threadIdx.x;
    if (i >= 256 * 128) return;
    int n = i >> 7, k = i & 127;
    Wt[i] = rna_tf32(W[k * 256 + n]);
}
// Bt[(h*64+o)*fin + k] = rna(w[(h*fin + k)*64 + o]),  w is (H, fin, 64)
__global__ void repack_round(float* __restrict__ Bt, const float* __restrict__ w, int fin) {
    int i = blockIdx.x * blockDim.x + threadIdx.x;
    if (i >= fin * 512) return;
    int n = i / fin, k = i % fin;
    int h = n >> 6, o = n & 63;
    Bt[i] = rna_tf32(w[((size_t)(h * fin + k) << 6) + o]);
}
// in-place ELU + tf32 round on x0
__global__ void elu_round(float* __restrict__ x, int n) {
    int i = blockIdx.x * blockDim.x + threadIdx.x;
    if (i < n) x[i] = rna_tf32(eluf(x[i]));
}

// ---------------- attention / scatter kernels ----------------
__global__ void st_kernel(const float* __restrict__ hp,
                          const float* __restrict__ asrc,
                          const float* __restrict__ atrg) {
    int idx = blockIdx.x * blockDim.x + threadIdx.x;
    if (idx >= NN * HH) return;
    int h = idx & 7;
    const float4* v = (const float4*)(hp + (size_t)idx * 64);
    const float4* a = (const float4*)(asrc + h * 64);
    const float4* b = (const float4*)(atrg + h * 64);
    float s = 0.f, t = 0.f;
#pragma unroll
    for (int k = 0; k < 16; k++) {
        float4 x = v[k], aa = a[k], bb = b[k];
        s += x.x * aa.x + x.y * aa.y + x.z * aa.z + x.w * aa.w;
        t += x.x * bb.x + x.y * bb.y + x.z * bb.z + x.w * bb.w;
    }
    g_s[idx] = s;
    g_t[idx] = t;
}

__global__ void zero_agg(int sel) {
    float* p = (sel == 0) ? g_x0 : ((sel == 1) ? g_o1a : g_o1b);
    int i = blockIdx.x * blockDim.x + threadIdx.x;
    if (i < NN * HF / 4) ((float4*)p)[i] = make_float4(0.f, 0.f, 0.f, 0.f);
    if (i < NN * HH) g_denom[i] = 0.f;
}

__device__ __forceinline__ float lre(float v) {
    return __expf(fmaxf(v, 0.2f * v));   // global max-shift cancels in alpha
}

__global__ void edge_attn(const int* __restrict__ src, const int* __restrict__ trg) {
    int e = blockIdx.x * blockDim.x + threadIdx.x;
    if (e >= EE) return;
    int si = src[e], ti = trg[e];
    float4 s0 = *(const float4*)(g_s + si * 8);
    float4 s1 = *(const float4*)(g_s + si * 8 + 4);
    float4 t0 = *(const float4*)(g_t + ti * 8);
    float4 t1 = *(const float4*)(g_t + ti * 8 + 4);
    float4 e0, e1;
    e0.x = lre(s0.x + t0.x); e0.y = lre(s0.y + t0.y);
    e0.z = lre(s0.z + t0.z); e0.w = lre(s0.w + t0.w);
    e1.x = lre(s1.x + t1.x); e1.y = lre(s1.y + t1.y);
    e1.z = lre(s1.z + t1.z); e1.w = lre(s1.w + t1.w);
    *(float4*)(g_ex + (size_t)e * 8)     = e0;
    *(float4*)(g_ex + (size_t)e * 8 + 4) = e1;
    red4(g_denom + ti * 8, e0);
    red4(g_denom + ti * 8 + 4, e1);
}

__global__ __launch_bounds__(256) void scatter(const int* __restrict__ src,
                                               const int* __restrict__ trg,
                                               const float* __restrict__ hp,
                                               float* __restrict__ out) {
    int w = (blockIdx.x * 256 + threadIdx.x) >> 5;
    int lane = threadIdx.x & 31;
    if (w >= EE) return;
    int si = src[w], ti = trg[w];
    float alpha = 0.f;
    if (lane < 8)
        alpha = g_ex[(size_t)w * 8 + lane] / (g_denom[ti * 8 + lane] + 1e-16f);
    const float4* hv = (const float4*)(hp + (size_t)si * 512);
    float* ob = out + (size_t)ti * 512;
#pragma unroll
    for (int j = 0; j < 4; j++) {
        int c = lane + 32 * j;
        float al = __shfl_sync(0xffffffffu, alpha, c >> 4);
        float4 v = hv[c];
        v.x *= al; v.y *= al; v.z *= al; v.w *= al;
        red4(ob + (c << 2), v);
    }
}

__global__ void fa_kernel(const float* __restrict__ trans1, const float* __restrict__ aw1) {
    int o = threadIdx.x;
    float acc = 0.f;
    for (int f = 0; f < FUNI; f++) acc += trans1[f] * aw1[f * 64 + o];
    g_fa[o] = acc;
}

__global__ __launch_bounds__(64) void final_kernel(const float* __restrict__ aw2,
                                                   const float* __restrict__ am,
                                                   const float* __restrict__ fcw,
                                                   const float* __restrict__ fcb,
                                                   float* __restrict__ out) {
    __shared__ float ta[2][64];
    __shared__ float r0[64], r1[64];
    __shared__ float sc[2];
    int n = blockIdx.x, o = threadIdx.x;

    float m0 = 0.f, m1 = 0.f;
    const float* p0 = g_o1a + (size_t)n * 512 + o;
    const float* p1 = g_o1b + (size_t)n * 512 + o;
#pragma unroll
    for (int h = 0; h < 8; h++) { m0 += p0[h * 64]; m1 += p1[h * 64]; }
    m0 *= 0.125f; m1 *= 0.125f;
    ta[0][o] = m0; ta[1][o] = m1;
    __syncthreads();

    float amo = am[o];
    float fa = g_fa[o];
    {
        float acc0 = fa, acc1 = fa;
        for (int d = 0; d < 64; d++) {
            float w = aw2[d * 64 + o];
            acc0 += ta[0][d] * w;
            acc1 += ta[1][d] * w;
        }
        r0[o] = tanhf(acc0) * amo;
        r1[o] = tanhf(acc1) * amo;
    }
    __syncthreads();
    if (o == 0) {
        float s0 = 0.f, s1 = 0.f;
        for (int d = 0; d < 64; d++) { s0 += r0[d]; s1 += r1[d]; }
        sc[0] = s0; sc[1] = s1;
    }
    __syncthreads();
    float mx = fmaxf(sc[0], sc[1]);
    float b0 = __expf(sc[0] - mx), b1 = __expf(sc[1] - mx);
    float inv = 1.f / (b0 + b1);
    b0 *= inv; b1 *= inv;
    float fus = b0 * m0 + b1 * m1;

    r0[o] = m0 * fcw[o * 2 + 0] + m1 * fcw[(64 + o) * 2 + 0] + fus * fcw[(128 + o) * 2 + 0];
    r1[o] = m0 * fcw[o * 2 + 1] + m1 * fcw[(64 + o) * 2 + 1] + fus * fcw[(128 + o) * 2 + 1];
    __syncthreads();
    if (o == 0) {
        float l0 = fcb[0], l1 = fcb[1];
        for (int d = 0; d < 64; d++) { l0 += r0[d]; l1 += r1[d]; }
        float m = fmaxf(l0, l1);
        float lse = m + logf(__expf(l0 - m) + __expf(l1 - m));
        out[n * 2 + 0] = l0 - lse;
        out[n * 2 + 1] = l1 - lse;
    }
}

// ---------------- launcher ----------------
extern "C" void kernel_launch(void* const* d_in, const int* in_sizes, int n_in,
                              void* d_out, int out_size)
{
    const float* hemb0 = (const float*)d_in[0];
    const float* hemb1 = (const float*)d_in[1];
    const float* W0    = (const float*)d_in[2];
    const float* W1    = (const float*)d_in[3];
    const float* gw[2][2]    = {{(const float*)d_in[4],  (const float*)d_in[7]},
                                {(const float*)d_in[10], (const float*)d_in[13]}};
    const float* gasrc[2][2] = {{(const float*)d_in[5],  (const float*)d_in[8]},
                                {(const float*)d_in[11], (const float*)d_in[14]}};
    const float* gatrg[2][2] = {{(const float*)d_in[6],  (const float*)d_in[9]},
                                {(const float*)d_in[12], (const float*)d_in[15]}};
    const float* aw1 = (const float*)d_in[16];
    const float* aw2 = (const float*)d_in[17];
    const float* am  = (const float*)d_in[18];
    const float* fcw = (const float*)d_in[19];
    const float* fcb = (const float*)d_in[20];
    const int* edge[2] = {(const int*)d_in[21], (const int*)d_in[22]};

    float *trans[2], *Bp, *hp, *x0, *o1[2], *exbuf;
    cudaGetSymbolAddress((void**)&trans[0], g_trans0);
    cudaGetSymbolAddress((void**)&trans[1], g_trans1);
    cudaGetSymbolAddress((void**)&Bp,  g_Bp);
    cudaGetSymbolAddress((void**)&hp,  g_hp);
    cudaGetSymbolAddress((void**)&x0,  g_x0);
    cudaGetSymbolAddress((void**)&o1[0], g_o1a);
    cudaGetSymbolAddress((void**)&o1[1], g_o1b);
    cudaGetSymbolAddress((void**)&exbuf, g_ex);

    cudaFuncSetAttribute(gemm_mma, cudaFuncAttributeMaxDynamicSharedMemorySize, SMEM_GEMM);

    const dim3 gridT(FUNI / 128, (NN + 127) / 128);   // trans GEMMs
    const dim3 gridH(HF / 128,  (NN + 127) / 128);    // layer GEMMs

    // round hemb inputs to tf32 into scratch (g_ex and g_hp are free this early)
    round_tf32_k<<<(NN * 128 + 255) / 256, 256>>>(exbuf, hemb0, NN * 128);
    round_tf32_k<<<(NN * 128 + 255) / 256, 256>>>(hp,    hemb1, NN * 128);

    // trans GEMMs (round outputs: they feed layer-0 GEMM A)
    transpose_round<<<(256 * 128 + 255) / 256, 256>>>(Bp, W0);
    gemm_mma<<<gridT, 256, SMEM_GEMM>>>(exbuf, Bp, trans[0], NN, 128, FUNI, 1);
    transpose_round<<<(256 * 128 + 255) / 256, 256>>>(Bp, W1);
    gemm_mma<<<gridT, 256, SMEM_GEMM>>>(hp, Bp, trans[1], NN, 128, FUNI, 1);

    for (int t = 0; t < 2; t++) {
        const int* src = edge[t];
        const int* trg = edge[t] + EE;

        // ---- layer 0 (fin = 256) ----
        repack_round<<<(FUNI * 512 + 255) / 256, 256>>>(Bp, gw[t][0], FUNI);
        gemm_mma<<<gridH, 256, SMEM_GEMM>>>(trans[t], Bp, hp, NN, FUNI, HF, 0);
        st_kernel<<<(NN * HH + 255) / 256, 256>>>(hp, gasrc[t][0], gatrg[t][0]);
        zero_agg<<<(NN * HF / 4 + 255) / 256, 256>>>(0);
        edge_attn<<<(EE + 255) / 256, 256>>>(src, trg);
        scatter<<<(EE + 7) / 8, 256>>>(src, trg, hp, x0);

        // ---- layer 1 (fin = 512): ELU + tf32 round on aggregated x0 ----
        elu_round<<<(NN * HF + 255) / 256, 256>>>(x0, NN * HF);
        repack_round<<<(HF * 512 + 255) / 256, 256>>>(Bp, gw[t][1], HF);
        gemm_mma<<<gridH, 256, SMEM_GEMM>>>(x0, Bp, hp, NN, HF, HF, 0);
        st_kernel<<<(NN * HH + 255) / 256, 256>>>(hp, gasrc[t][1], gatrg[t][1]);
        zero_agg<<<(NN * HF / 4 + 255) / 256, 256>>>(1 + t);
        edge_attn<<<(EE + 255) / 256, 256>>>(src, trg);
        scatter<<<(EE + 7) / 8, 256>>>(src, trg, hp, o1[t]);
    }

    fa_kernel<<<1, 64>>>(trans[1], aw1);
    final_kernel<<<NN, 64>>>(aw2, am, fcw, fcb, (float*)d_out);
}

// round 7
// speedup vs baseline: 1.9910x; 1.2344x over previous
#include <cuda_runtime.h>
#include <cstdint>
#include <cstddef>

#define NN   20000
#define EE   320000
#define HH   8
#define FUNI 256
#define FOUT 64
#define HF   512   // H*FOUT

// ---------------- scratch (device globals; no runtime allocation) ----------------
__device__ float g_trans0[NN * FUNI];
__device__ float g_trans1[NN * FUNI];
__device__ float g_Bp[512 * 512];         // repacked GAT weight, [N][K] K-major, tf32-rounded
__device__ float g_hp[NN * HF];           // projected features; also temp for rounded hemb1
__device__ float g_x0[NN * HF];           // layer-0 aggregated output
__device__ float g_o1a[NN * HF];          // layer-1 aggregated output, type 0
__device__ float g_o1b[NN * HF];          // layer-1 aggregated output, type 1
__device__ float g_s[NN * HH];
__device__ float g_t[NN * HH];
__device__ float g_tmp0[NN * 128];        // rounded hemb0
__device__ float g_fa[FOUT];

// CSR scratch
__device__ int g_cnt[NN];
__device__ int g_rowptr[2][NN + 1];
__device__ int g_woff[NN];
__device__ int g_csr[2][EE];

// ---------------- helpers ----------------
__device__ __forceinline__ uint32_t smem_to_u32(const void* p) {
    uint32_t a;
    asm("{ .reg .u64 t; cvta.to.shared.u64 t, %1; cvt.u32.u64 %0, t; }" : "=r"(a) : "l"(p));
    return a;
}
__device__ __forceinline__ void cp16(uint32_t saddr, const void* g) {
    asm volatile("cp.async.cg.shared.global [%0], [%1], 16;" :: "r"(saddr), "l"(g));
}
__device__ __forceinline__ void sts_zero16(uint32_t saddr) {
    asm volatile("st.shared.v4.b32 [%0], {%1,%1,%1,%1};" :: "r"(saddr), "r"(0u));
}
#define CP_COMMIT() asm volatile("cp.async.commit_group;" ::: "memory")
#define CP_WAIT2()  asm volatile("cp.async.wait_group 2;" ::: "memory")

__device__ __forceinline__ float rna_tf32(float x) {
    uint32_t u; asm("cvt.rna.tf32.f32 %0, %1;" : "=r"(u) : "f"(x));
    return __uint_as_float(u);
}
__device__ __forceinline__ float eluf(float x) { return x > 0.f ? x : (__expf(x) - 1.f); }
__device__ __forceinline__ void mma_tf32(float* c, const uint32_t* a, const uint32_t* b) {
    asm volatile("mma.sync.aligned.m16n8k8.row.col.f32.tf32.tf32.f32 "
                 "{%0,%1,%2,%3}, {%4,%5,%6,%7}, {%8,%9}, {%0,%1,%2,%3};"
                 : "+f"(c[0]), "+f"(c[1]), "+f"(c[2]), "+f"(c[3])
                 : "r"(a[0]), "r"(a[1]), "r"(a[2]), "r"(a[3]), "r"(b[0]), "r"(b[1]));
}

// ---------------- mma.sync tf32 GEMM: C[M,NC] = A[M,K] @ Bt[NC,K]^T ----------------
#define KC      16
#define STAGES  3
#define STRIDEF 20
#define TILEF   (128 * STRIDEF)
#define STAGEF  (2 * TILEF)
#define SMEM_GEMM (STAGES * STAGEF * 4)    // 61440 bytes

__global__ __launch_bounds__(256, 2)
void gemm_mma(const float* __restrict__ A, const float* __restrict__ Bt,
              float* __restrict__ C, int M, int K, int NC, int round_out)
{
    extern __shared__ float sm[];
    const int tid  = threadIdx.x;
    const int wid  = tid >> 5, lane = tid & 31;
    const int g    = lane >> 2, t = lane & 3;
    const int bm   = blockIdx.y << 7, bn = blockIdx.x << 7;
    const int m0   = (wid >> 1) * 32;
    const int n0   = (wid & 1) * 64;
    const int P    = K >> 4;

    const uint32_t sb = smem_to_u32(sm);
    const int lrow = tid >> 2;
    const int lc4  = tid & 3;

    float acc[2][8][4];
#pragma unroll
    for (int i = 0; i < 2; i++)
#pragma unroll
        for (int j = 0; j < 8; j++)
#pragma unroll
            for (int q = 0; q < 4; q++) acc[i][j][q] = 0.f;

#pragma unroll
    for (int s = 0; s < STAGES; s++) {
        uint32_t stb = sb + s * STAGEF * 4;
#pragma unroll
        for (int j = 0; j < 2; j++) {
            int row = lrow + j * 64;
            uint32_t sa = stb + (row * STRIDEF + lc4 * 4) * 4;
            int ar = bm + row;
            if (ar < M) cp16(sa, A + (size_t)ar * K + s * KC + lc4 * 4);
            else        sts_zero16(sa);
            uint32_t sbB = stb + TILEF * 4 + (row * STRIDEF + lc4 * 4) * 4;
            cp16(sbB, Bt + (size_t)(bn + row) * K + s * KC + lc4 * 4);
        }
        CP_COMMIT();
    }

    for (int p = 0; p < P; p++) {
        const int slot = p % STAGES;
        CP_WAIT2();
        __syncthreads();
        const float* As = sm + slot * STAGEF;
        const float* Bs = As + TILEF;

#pragma unroll
        for (int ks = 0; ks < 2; ks++) {
            uint32_t a[2][4], b[8][2];
#pragma unroll
            for (int i = 0; i < 2; i++) {
                const float* ab = As + (m0 + i * 16 + g) * STRIDEF + ks * 8 + t;
                a[i][0] = __float_as_uint(ab[0]);
                a[i][1] = __float_as_uint(ab[8 * STRIDEF]);
                a[i][2] = __float_as_uint(ab[4]);
                a[i][3] = __float_as_uint(ab[8 * STRIDEF + 4]);
            }
#pragma unroll
            for (int j = 0; j < 8; j++) {
                const float* bb = Bs + (n0 + j * 8 + g) * STRIDEF + ks * 8 + t;
                b[j][0] = __float_as_uint(bb[0]);
                b[j][1] = __float_as_uint(bb[4]);
            }
#pragma unroll
            for (int i = 0; i < 2; i++)
#pragma unroll
                for (int j = 0; j < 8; j++)
                    mma_tf32(acc[i][j], a[i], b[j]);
        }
        __syncthreads();

        int np = p + STAGES;
        if (np < P) {
            uint32_t stb = sb + slot * STAGEF * 4;
#pragma unroll
            for (int j = 0; j < 2; j++) {
                int row = lrow + j * 64;
                uint32_t sa = stb + (row * STRIDEF + lc4 * 4) * 4;
                int ar = bm + row;
                if (ar < M) cp16(sa, A + (size_t)ar * K + np * KC + lc4 * 4);
                else        sts_zero16(sa);
                uint32_t sbB = stb + TILEF * 4 + (row * STRIDEF + lc4 * 4) * 4;
                cp16(sbB, Bt + (size_t)(bn + row) * K + np * KC + lc4 * 4);
            }
        }
        CP_COMMIT();
    }

#pragma unroll
    for (int i = 0; i < 2; i++) {
        int r0 = bm + m0 + i * 16 + g;
#pragma unroll
        for (int j = 0; j < 8; j++) {
            int col = bn + n0 + j * 8 + 2 * t;
            float c0 = acc[i][j][0], c1 = acc[i][j][1];
            float c2 = acc[i][j][2], c3 = acc[i][j][3];
            if (round_out) {
                c0 = rna_tf32(c0); c1 = rna_tf32(c1);
                c2 = rna_tf32(c2); c3 = rna_tf32(c3);
            }
            if (r0 < M)
                *(float2*)(C + (size_t)r0 * NC + col) = make_float2(c0, c1);
            if (r0 + 8 < M)
                *(float2*)(C + (size_t)(r0 + 8) * NC + col) = make_float2(c2, c3);
        }
    }
}

// ---------------- CSR build ----------------
__global__ void zero_cnt() {
    int i = blockIdx.x * blockDim.x + threadIdx.x;
    if (i < NN) g_cnt[i] = 0;
}
__global__ void hist_kernel(const int* __restrict__ trg) {
    int e = blockIdx.x * blockDim.x + threadIdx.x;
    if (e < EE) atomicAdd(&g_cnt[trg[e]], 1);
}
#define SCAN_CH 20
__global__ __launch_bounds__(1024) void scan_kernel(int t) {
    __shared__ int part[1024];
    int tid = threadIdx.x;
    int base = tid * SCAN_CH;
    int loc[SCAN_CH];
    int s = 0;
#pragma unroll
    for (int i = 0; i < SCAN_CH; i++) {
        int idx = base + i;
        int v = (idx < NN) ? g_cnt[idx] : 0;
        loc[i] = s;
        s += v;
    }
    part[tid] = s;
    __syncthreads();
    for (int d = 1; d < 1024; d <<= 1) {
        int v = (tid >= d) ? part[tid - d] : 0;
        __syncthreads();
        part[tid] += v;
        __syncthreads();
    }
    int excl = part[tid] - s;   // exclusive prefix of this chunk
#pragma unroll
    for (int i = 0; i < SCAN_CH; i++) {
        int idx = base + i;
        if (idx < NN) {
            int v = loc[i] + excl;
            g_rowptr[t][idx] = v;
            g_woff[idx] = v;
        }
    }
    if (tid == 1023) g_rowptr[t][NN] = part[1023];
}
__global__ void fill_kernel(const int* __restrict__ src, const int* __restrict__ trg, int t) {
    int e = blockIdx.x * blockDim.x + threadIdx.x;
    if (e >= EE) return;
    int p = atomicAdd(&g_woff[trg[e]], 1);
    g_csr[t][p] = src[e];
}

// ---------------- s/t projections ----------------
__global__ void st_kernel(const float* __restrict__ hp,
                          const float* __restrict__ asrc,
                          const float* __restrict__ atrg) {
    int idx = blockIdx.x * blockDim.x + threadIdx.x;
    if (idx >= NN * HH) return;
    int h = idx & 7;
    const float4* v = (const float4*)(hp + (size_t)idx * 64);
    const float4* a = (const float4*)(asrc + h * 64);
    const float4* b = (const float4*)(atrg + h * 64);
    float s = 0.f, t = 0.f;
#pragma unroll
    for (int k = 0; k < 16; k++) {
        float4 x = v[k], aa = a[k], bb = b[k];
        s += x.x * aa.x + x.y * aa.y + x.z * aa.z + x.w * aa.w;
        t += x.x * bb.x + x.y * bb.y + x.z * bb.z + x.w * bb.w;
    }
    g_s[idx] = s;
    g_t[idx] = t;
}

// ---------------- gather-aggregate: warp per target node ----------------
// out[n] = (sum_e ex_e * hp[src_e]) / (sum_e ex_e + 1e-16), per head
__global__ __launch_bounds__(256) void gather_agg(const int* __restrict__ csr,
                                                  const int* __restrict__ rowptr,
                                                  const float* __restrict__ hp,
                                                  float* __restrict__ out)
{
    int node = (blockIdx.x * 256 + threadIdx.x) >> 5;
    int lane = threadIdx.x & 31;
    if (node >= NN) return;
    int beg = rowptr[node], end = rowptr[node + 1];

    float tval = (lane < 8) ? g_t[node * 8 + lane] : 0.f;
    float denom = 0.f;                       // lanes 0..7: per-head denominator
    float4 acc[4];
#pragma unroll
    for (int j = 0; j < 4; j++) acc[j] = make_float4(0.f, 0.f, 0.f, 0.f);

    int srcp = (beg < end) ? csr[beg] : 0;
    for (int p = beg; p < end; p++) {
        int nxt = (p + 1 < end) ? csr[p + 1] : 0;
        float ex = 0.f;
        if (lane < 8) {
            float v = g_s[srcp * 8 + lane] + tval;
            ex = __expf(fmaxf(v, 0.2f * v));   // global max-shift cancels in alpha
            denom += ex;
        }
        const float4* hv = (const float4*)(hp + (size_t)srcp * 512);
#pragma unroll
        for (int j = 0; j < 4; j++) {
            int c = lane + 32 * j;
            float al = __shfl_sync(0xffffffffu, ex, c >> 4);
            float4 v = hv[c];
            acc[j].x += al * v.x; acc[j].y += al * v.y;
            acc[j].z += al * v.z; acc[j].w += al * v.w;
        }
        srcp = nxt;
    }

    float4* ob = (float4*)(out + (size_t)node * 512);
#pragma unroll
    for (int j = 0; j < 4; j++) {
        int c = lane + 32 * j;
        float dn = __shfl_sync(0xffffffffu, denom, c >> 4) + 1e-16f;
        float inv = 1.f / dn;
        float4 v = acc[j];
        v.x *= inv; v.y *= inv; v.z *= inv; v.w *= inv;
        ob[c] = v;
    }
}

// ---------------- small prep kernels ----------------
__global__ void round_tf32_k(float* __restrict__ dst, const float* __restrict__ src, int n) {
    int i = blockIdx.x * blockDim.x + threadIdx.x;
    if (i < n) dst[i] = rna_tf32(src[i]);
}
__global__ void transpose_round(float* __restrict__ Wt, const float* __restrict__ W) {
    int i = blockIdx.x * blockDim.x + threadIdx.x;
    if (i >= 256 * 128) return;
    int n = i >> 7, k = i & 127;
    Wt[i] = rna_tf32(W[k * 256 + n]);
}
__global__ void repack_round(float* __restrict__ Bt, const float* __restrict__ w, int fin) {
    int i = blockIdx.x * blockDim.x + threadIdx.x;
    if (i >= fin * 512) return;
    int n = i / fin, k = i % fin;
    int h = n >> 6, o = n & 63;
    Bt[i] = rna_tf32(w[((size_t)(h * fin + k) << 6) + o]);
}
__global__ void elu_round(float* __restrict__ x, int n) {
    int i = blockIdx.x * blockDim.x + threadIdx.x;
    if (i < n) x[i] = rna_tf32(eluf(x[i]));
}

__global__ void fa_kernel(const float* __restrict__ trans1, const float* __restrict__ aw1) {
    int o = threadIdx.x;
    float acc = 0.f;
    for (int f = 0; f < FUNI; f++) acc += trans1[f] * aw1[f * 64 + o];
    g_fa[o] = acc;
}

__global__ __launch_bounds__(64) void final_kernel(const float* __restrict__ aw2,
                                                   const float* __restrict__ am,
                                                   const float* __restrict__ fcw,
                                                   const float* __restrict__ fcb,
                                                   float* __restrict__ out) {
    __shared__ float ta[2][64];
    __shared__ float r0[64], r1[64];
    __shared__ float sc[2];
    int n = blockIdx.x, o = threadIdx.x;

    float m0 = 0.f, m1 = 0.f;
    const float* p0 = g_o1a + (size_t)n * 512 + o;
    const float* p1 = g_o1b + (size_t)n * 512 + o;
#pragma unroll
    for (int h = 0; h < 8; h++) { m0 += p0[h * 64]; m1 += p1[h * 64]; }
    m0 *= 0.125f; m1 *= 0.125f;
    ta[0][o] = m0; ta[1][o] = m1;
    __syncthreads();

    float amo = am[o];
    float fa = g_fa[o];
    {
        float acc0 = fa, acc1 = fa;
        for (int d = 0; d < 64; d++) {
            float w = aw2[d * 64 + o];
            acc0 += ta[0][d] * w;
            acc1 += ta[1][d] * w;
        }
        r0[o] = tanhf(acc0) * amo;
        r1[o] = tanhf(acc1) * amo;
    }
    __syncthreads();
    if (o == 0) {
        float s0 = 0.f, s1 = 0.f;
        for (int d = 0; d < 64; d++) { s0 += r0[d]; s1 += r1[d]; }
        sc[0] = s0; sc[1] = s1;
    }
    __syncthreads();
    float mx = fmaxf(sc[0], sc[1]);
    float b0 = __expf(sc[0] - mx), b1 = __expf(sc[1] - mx);
    float inv = 1.f / (b0 + b1);
    b0 *= inv; b1 *= inv;
    float fus = b0 * m0 + b1 * m1;

    r0[o] = m0 * fcw[o * 2 + 0] + m1 * fcw[(64 + o) * 2 + 0] + fus * fcw[(128 + o) * 2 + 0];
    r1[o] = m0 * fcw[o * 2 + 1] + m1 * fcw[(64 + o) * 2 + 1] + fus * fcw[(128 + o) * 2 + 1];
    __syncthreads();
    if (o == 0) {
        float l0 = fcb[0], l1 = fcb[1];
        for (int d = 0; d < 64; d++) { l0 += r0[d]; l1 += r1[d]; }
        float m = fmaxf(l0, l1);
        float lse = m + logf(__expf(l0 - m) + __expf(l1 - m));
        out[n * 2 + 0] = l0 - lse;
        out[n * 2 + 1] = l1 - lse;
    }
}

// ---------------- launcher ----------------
extern "C" void kernel_launch(void* const* d_in, const int* in_sizes, int n_in,
                              void* d_out, int out_size)
{
    const float* hemb0 = (const float*)d_in[0];
    const float* hemb1 = (const float*)d_in[1];
    const float* W0    = (const float*)d_in[2];
    const float* W1    = (const float*)d_in[3];
    const float* gw[2][2]    = {{(const float*)d_in[4],  (const float*)d_in[7]},
                                {(const float*)d_in[10], (const float*)d_in[13]}};
    const float* gasrc[2][2] = {{(const float*)d_in[5],  (const float*)d_in[8]},
                                {(const float*)d_in[11], (const float*)d_in[14]}};
    const float* gatrg[2][2] = {{(const float*)d_in[6],  (const float*)d_in[9]},
                                {(const float*)d_in[12], (const float*)d_in[15]}};
    const float* aw1 = (const float*)d_in[16];
    const float* aw2 = (const float*)d_in[17];
    const float* am  = (const float*)d_in[18];
    const float* fcw = (const float*)d_in[19];
    const float* fcb = (const float*)d_in[20];
    const int* edge[2] = {(const int*)d_in[21], (const int*)d_in[22]};

    float *trans[2], *Bp, *hp, *x0, *o1[2], *tmp0;
    int *csr[2], *rowptr[2];
    cudaGetSymbolAddress((void**)&trans[0], g_trans0);
    cudaGetSymbolAddress((void**)&trans[1], g_trans1);
    cudaGetSymbolAddress((void**)&Bp,  g_Bp);
    cudaGetSymbolAddress((void**)&hp,  g_hp);
    cudaGetSymbolAddress((void**)&x0,  g_x0);
    cudaGetSymbolAddress((void**)&o1[0], g_o1a);
    cudaGetSymbolAddress((void**)&o1[1], g_o1b);
    cudaGetSymbolAddress((void**)&tmp0, g_tmp0);
    {
        int* base;
        cudaGetSymbolAddress((void**)&base, g_csr);
        csr[0] = base; csr[1] = base + EE;
        cudaGetSymbolAddress((void**)&base, g_rowptr);
        rowptr[0] = base; rowptr[1] = base + (NN + 1);
    }

    cudaFuncSetAttribute(gemm_mma, cudaFuncAttributeMaxDynamicSharedMemorySize, SMEM_GEMM);

    const dim3 gridT(FUNI / 128, (NN + 127) / 128);
    const dim3 gridH(HF / 128,  (NN + 127) / 128);

    // CSR build (per type; reused by both layers)
    for (int t = 0; t < 2; t++) {
        const int* src = edge[t];
        const int* trg = edge[t] + EE;
        zero_cnt<<<(NN + 255) / 256, 256>>>();
        hist_kernel<<<(EE + 255) / 256, 256>>>(trg);
        scan_kernel<<<1, 1024>>>(t);
        fill_kernel<<<(EE + 255) / 256, 256>>>(src, trg, t);
    }

    // round hemb inputs to tf32
    round_tf32_k<<<(NN * 128 + 255) / 256, 256>>>(tmp0, hemb0, NN * 128);
    round_tf32_k<<<(NN * 128 + 255) / 256, 256>>>(hp,   hemb1, NN * 128);

    // trans GEMMs (round outputs: they feed layer-0 GEMM A)
    transpose_round<<<(256 * 128 + 255) / 256, 256>>>(Bp, W0);
    gemm_mma<<<gridT, 256, SMEM_GEMM>>>(tmp0, Bp, trans[0], NN, 128, FUNI, 1);
    transpose_round<<<(256 * 128 + 255) / 256, 256>>>(Bp, W1);
    gemm_mma<<<gridT, 256, SMEM_GEMM>>>(hp, Bp, trans[1], NN, 128, FUNI, 1);

    for (int t = 0; t < 2; t++) {
        // ---- layer 0 (fin = 256) ----
        repack_round<<<(FUNI * 512 + 255) / 256, 256>>>(Bp, gw[t][0], FUNI);
        gemm_mma<<<gridH, 256, SMEM_GEMM>>>(trans[t], Bp, hp, NN, FUNI, HF, 0);
        st_kernel<<<(NN * HH + 255) / 256, 256>>>(hp, gasrc[t][0], gatrg[t][0]);
        gather_agg<<<(NN * 32 + 255) / 256, 256>>>(csr[t], rowptr[t], hp, x0);

        // ---- layer 1 (fin = 512) ----
        elu_round<<<(NN * HF + 255) / 256, 256>>>(x0, NN * HF);
        repack_round<<<(HF * 512 + 255) / 256, 256>>>(Bp, gw[t][1], HF);
        gemm_mma<<<gridH, 256, SMEM_GEMM>>>(x0, Bp, hp, NN, HF, HF, 0);
        st_kernel<<<(NN * HH + 255) / 256, 256>>>(hp, gasrc[t][1], gatrg[t][1]);
        gather_agg<<<(NN * 32 + 255) / 256, 256>>>(csr[t], rowptr[t], hp, o1[t]);
    }

    fa_kernel<<<1, 64>>>(trans[1], aw1);
    final_kernel<<<NN, 64>>>(aw2, am, fcw, fcb, (float*)d_out);
}

// round 9
// speedup vs baseline: 2.1338x; 1.0717x over previous
#include <cuda_runtime.h>
#include <cstdint>
#include <cstddef>

#define NN   20000
#define EE   320000
#define HH   8
#define FUNI 256
#define FOUT 64
#define HF   512   // H*FOUT

// ---------------- scratch (device globals; no runtime allocation) ----------------
__device__ float g_trans0[NN * FUNI];
__device__ float g_trans1[NN * FUNI];
__device__ float g_Bp[512 * 512];         // repacked GAT weight, [N][K] K-major, tf32-rounded
__device__ float g_hp[NN * HF];           // projected features; also temp for rounded hemb1
__device__ uint32_t g_hpb[NN * HF / 2];   // bf16x2-packed copy of hp for the gather
__device__ float g_x0[NN * HF];           // layer-0 aggregated output
__device__ float g_o1a[NN * HF];          // layer-1 aggregated output, type 0
__device__ float g_o1b[NN * HF];          // layer-1 aggregated output, type 1
__device__ float g_s[NN * HH];
__device__ float g_t[NN * HH];
__device__ float g_tmp0[NN * 128];        // rounded hemb0
__device__ float g_fa[FOUT];

// CSR scratch
__device__ int g_cnt[NN];
__device__ int g_rowptr[2][NN + 1];
__device__ int g_woff[NN];
__device__ int g_csr[2][EE];

// ---------------- helpers ----------------
__device__ __forceinline__ uint32_t smem_to_u32(const void* p) {
    uint32_t a;
    asm("{ .reg .u64 t; cvta.to.shared.u64 t, %1; cvt.u32.u64 %0, t; }" : "=r"(a) : "l"(p));
    return a;
}
__device__ __forceinline__ void cp16(uint32_t saddr, const void* g) {
    asm volatile("cp.async.cg.shared.global [%0], [%1], 16;" :: "r"(saddr), "l"(g));
}
__device__ __forceinline__ void sts_zero16(uint32_t saddr) {
    asm volatile("st.shared.v4.b32 [%0], {%1,%1,%1,%1};" :: "r"(saddr), "r"(0u));
}
#define CP_COMMIT() asm volatile("cp.async.commit_group;" ::: "memory")
#define CP_WAIT2()  asm volatile("cp.async.wait_group 2;" ::: "memory")

__device__ __forceinline__ float rna_tf32(float x) {
    uint32_t u; asm("cvt.rna.tf32.f32 %0, %1;" : "=r"(u) : "f"(x));
    return __uint_as_float(u);
}
// pack two fp32 -> bf16x2 (lo = a, hi = b)
__device__ __forceinline__ uint32_t pack_bf16x2(float a, float b) {
    uint32_t r;
    asm("cvt.rn.bf16x2.f32 %0, %1, %2;" : "=r"(r) : "f"(b), "f"(a));
    return r;
}
// unpack bf16x2 -> two fp32 (exact)
__device__ __forceinline__ float bf_lo(uint32_t u) { return __uint_as_float(u << 16); }
__device__ __forceinline__ float bf_hi(uint32_t u) { return __uint_as_float(u & 0xffff0000u); }

__device__ __forceinline__ float eluf(float x) { return x > 0.f ? x : (__expf(x) - 1.f); }
__device__ __forceinline__ void mma_tf32(float* c, const uint32_t* a, const uint32_t* b) {
    asm volatile("mma.sync.aligned.m16n8k8.row.col.f32.tf32.tf32.f32 "
                 "{%0,%1,%2,%3}, {%4,%5,%6,%7}, {%8,%9}, {%0,%1,%2,%3};"
                 : "+f"(c[0]), "+f"(c[1]), "+f"(c[2]), "+f"(c[3])
                 : "r"(a[0]), "r"(a[1]), "r"(a[2]), "r"(a[3]), "r"(b[0]), "r"(b[1]));
}

// ---------------- mma.sync tf32 GEMM: C[M,NC] = A[M,K] @ Bt[NC,K]^T ----------------
#define KC      16
#define STAGES  3
#define STRIDEF 20
#define TILEF   (128 * STRIDEF)
#define STAGEF  (2 * TILEF)
#define SMEM_GEMM (STAGES * STAGEF * 4)    // 61440 bytes

__global__ __launch_bounds__(256, 2)
void gemm_mma(const float* __restrict__ A, const float* __restrict__ Bt,
              float* __restrict__ C, int M, int K, int NC, int round_out)
{
    extern __shared__ float sm[];
    const int tid  = threadIdx.x;
    const int wid  = tid >> 5, lane = tid & 31;
    const int g    = lane >> 2, t = lane & 3;
    const int bm   = blockIdx.y << 7, bn = blockIdx.x << 7;
    const int m0   = (wid >> 1) * 32;
    const int n0   = (wid & 1) * 64;
    const int P    = K >> 4;

    const uint32_t sb = smem_to_u32(sm);
    const int lrow = tid >> 2;
    const int lc4  = tid & 3;

    float acc[2][8][4];
#pragma unroll
    for (int i = 0; i < 2; i++)
#pragma unroll
        for (int j = 0; j < 8; j++)
#pragma unroll
            for (int q = 0; q < 4; q++) acc[i][j][q] = 0.f;

#pragma unroll
    for (int s = 0; s < STAGES; s++) {
        uint32_t stb = sb + s * STAGEF * 4;
#pragma unroll
        for (int j = 0; j < 2; j++) {
            int row = lrow + j * 64;
            uint32_t sa = stb + (row * STRIDEF + lc4 * 4) * 4;
            int ar = bm + row;
            if (ar < M) cp16(sa, A + (size_t)ar * K + s * KC + lc4 * 4);
            else        sts_zero16(sa);
            uint32_t sbB = stb + TILEF * 4 + (row * STRIDEF + lc4 * 4) * 4;
            cp16(sbB, Bt + (size_t)(bn + row) * K + s * KC + lc4 * 4);
        }
        CP_COMMIT();
    }

    for (int p = 0; p < P; p++) {
        const int slot = p % STAGES;
        CP_WAIT2();
        __syncthreads();
        const float* As = sm + slot * STAGEF;
        const float* Bs = As + TILEF;

#pragma unroll
        for (int ks = 0; ks < 2; ks++) {
            uint32_t a[2][4], b[8][2];
#pragma unroll
            for (int i = 0; i < 2; i++) {
                const float* ab = As + (m0 + i * 16 + g) * STRIDEF + ks * 8 + t;
                a[i][0] = __float_as_uint(ab[0]);
                a[i][1] = __float_as_uint(ab[8 * STRIDEF]);
                a[i][2] = __float_as_uint(ab[4]);
                a[i][3] = __float_as_uint(ab[8 * STRIDEF + 4]);
            }
#pragma unroll
            for (int j = 0; j < 8; j++) {
                const float* bb = Bs + (n0 + j * 8 + g) * STRIDEF + ks * 8 + t;
                b[j][0] = __float_as_uint(bb[0]);
                b[j][1] = __float_as_uint(bb[4]);
            }
#pragma unroll
            for (int i = 0; i < 2; i++)
#pragma unroll
                for (int j = 0; j < 8; j++)
                    mma_tf32(acc[i][j], a[i], b[j]);
        }
        __syncthreads();

        int np = p + STAGES;
        if (np < P) {
            uint32_t stb = sb + slot * STAGEF * 4;
#pragma unroll
            for (int j = 0; j < 2; j++) {
                int row = lrow + j * 64;
                uint32_t sa = stb + (row * STRIDEF + lc4 * 4) * 4;
                int ar = bm + row;
                if (ar < M) cp16(sa, A + (size_t)ar * K + np * KC + lc4 * 4);
                else        sts_zero16(sa);
                uint32_t sbB = stb + TILEF * 4 + (row * STRIDEF + lc4 * 4) * 4;
                cp16(sbB, Bt + (size_t)(bn + row) * K + np * KC + lc4 * 4);
            }
        }
        CP_COMMIT();
    }

#pragma unroll
    for (int i = 0; i < 2; i++) {
        int r0 = bm + m0 + i * 16 + g;
#pragma unroll
        for (int j = 0; j < 8; j++) {
            int col = bn + n0 + j * 8 + 2 * t;
            float c0 = acc[i][j][0], c1 = acc[i][j][1];
            float c2 = acc[i][j][2], c3 = acc[i][j][3];
            if (round_out) {
                c0 = rna_tf32(c0); c1 = rna_tf32(c1);
                c2 = rna_tf32(c2); c3 = rna_tf32(c3);
            }
            if (r0 < M)
                *(float2*)(C + (size_t)r0 * NC + col) = make_float2(c0, c1);
            if (r0 + 8 < M)
                *(float2*)(C + (size_t)(r0 + 8) * NC + col) = make_float2(c2, c3);
        }
    }
}

// ---------------- CSR build ----------------
__global__ void zero_cnt() {
    int i = blockIdx.x * blockDim.x + threadIdx.x;
    if (i < NN) g_cnt[i] = 0;
}
__global__ void hist_kernel(const int* __restrict__ trg) {
    int e = blockIdx.x * blockDim.x + threadIdx.x;
    if (e < EE) atomicAdd(&g_cnt[trg[e]], 1);
}
#define SCAN_CH 20
__global__ __launch_bounds__(1024) void scan_kernel(int t) {
    __shared__ int part[1024];
    int tid = threadIdx.x;
    int base = tid * SCAN_CH;
    int loc[SCAN_CH];
    int s = 0;
#pragma unroll
    for (int i = 0; i < SCAN_CH; i++) {
        int idx = base + i;
        int v = (idx < NN) ? g_cnt[idx] : 0;
        loc[i] = s;
        s += v;
    }
    part[tid] = s;
    __syncthreads();
    for (int d = 1; d < 1024; d <<= 1) {
        int v = (tid >= d) ? part[tid - d] : 0;
        __syncthreads();
        part[tid] += v;
        __syncthreads();
    }
    int excl = part[tid] - s;
#pragma unroll
    for (int i = 0; i < SCAN_CH; i++) {
        int idx = base + i;
        if (idx < NN) {
            int v = loc[i] + excl;
            g_rowptr[t][idx] = v;
            g_woff[idx] = v;
        }
    }
    if (tid == 1023) g_rowptr[t][NN] = part[1023];
}
__global__ void fill_kernel(const int* __restrict__ src, const int* __restrict__ trg, int t) {
    int e = blockIdx.x * blockDim.x + threadIdx.x;
    if (e >= EE) return;
    int p = atomicAdd(&g_woff[trg[e]], 1);
    g_csr[t][p] = src[e];
}

// ---------------- s/t projections + bf16 copy of hp ----------------
__global__ void st_kernel(const float* __restrict__ hp,
                          const float* __restrict__ asrc,
                          const float* __restrict__ atrg) {
    int idx = blockIdx.x * blockDim.x + threadIdx.x;
    if (idx >= NN * HH) return;
    int h = idx & 7;
    const float4* v = (const float4*)(hp + (size_t)idx * 64);
    const float4* a = (const float4*)(asrc + h * 64);
    const float4* b = (const float4*)(atrg + h * 64);
    uint4* hb = (uint4*)(g_hpb + (size_t)idx * 32);
    float s = 0.f, t = 0.f;
#pragma unroll
    for (int k = 0; k < 16; k += 2) {
        float4 x0 = v[k], x1 = v[k + 1];
        float4 aa0 = a[k], aa1 = a[k + 1];
        float4 bb0 = b[k], bb1 = b[k + 1];
        s += x0.x * aa0.x + x0.y * aa0.y + x0.z * aa0.z + x0.w * aa0.w
           + x1.x * aa1.x + x1.y * aa1.y + x1.z * aa1.z + x1.w * aa1.w;
        t += x0.x * bb0.x + x0.y * bb0.y + x0.z * bb0.z + x0.w * bb0.w
           + x1.x * bb1.x + x1.y * bb1.y + x1.z * bb1.z + x1.w * bb1.w;
        uint4 pk;
        pk.x = pack_bf16x2(x0.x, x0.y);
        pk.y = pack_bf16x2(x0.z, x0.w);
        pk.z = pack_bf16x2(x1.x, x1.y);
        pk.w = pack_bf16x2(x1.z, x1.w);
        hb[k >> 1] = pk;
    }
    g_s[idx] = s;
    g_t[idx] = t;
}

// ---------------- gather-aggregate: warp per target node, bf16 messages ----------------
// out[n] = (sum_e ex_e * hpb[src_e]) / (sum_e ex_e + 1e-16), per head
__global__ __launch_bounds__(256) void gather_agg(const int* __restrict__ csr,
                                                  const int* __restrict__ rowptr,
                                                  const uint32_t* __restrict__ hpb,
                                                  float* __restrict__ out,
                                                  int do_elu)
{
    int node = (blockIdx.x * 256 + threadIdx.x) >> 5;
    int lane = threadIdx.x & 31;
    if (node >= NN) return;
    int beg = rowptr[node], end = rowptr[node + 1];

    float tval = (lane < 8) ? g_t[node * 8 + lane] : 0.f;
    float denom = 0.f;                       // lanes 0..7: per-head denominator
    float acc[2][8];
#pragma unroll
    for (int j = 0; j < 2; j++)
#pragma unroll
        for (int k = 0; k < 8; k++) acc[j][k] = 0.f;

    int srcp = (beg < end) ? csr[beg] : 0;
    for (int p = beg; p < end; p++) {
        int nxt = (p + 1 < end) ? csr[p + 1] : 0;
        float ex = 0.f;
        if (lane < 8) {
            float v = g_s[srcp * 8 + lane] + tval;
            ex = __expf(fmaxf(v, 0.2f * v));   // global max-shift cancels in alpha
            denom += ex;
        }
        const uint4* hv = (const uint4*)(hpb + (size_t)srcp * 256);
#pragma unroll
        for (int j = 0; j < 2; j++) {
            int c = lane + 32 * j;               // uint4 chunk 0..63 (8 bf16 each)
            float al = __shfl_sync(0xffffffffu, ex, c >> 3);   // head = c/8
            uint4 v = hv[c];
            acc[j][0] += al * bf_lo(v.x); acc[j][1] += al * bf_hi(v.x);
            acc[j][2] += al * bf_lo(v.y); acc[j][3] += al * bf_hi(v.y);
            acc[j][4] += al * bf_lo(v.z); acc[j][5] += al * bf_hi(v.z);
            acc[j][6] += al * bf_lo(v.w); acc[j][7] += al * bf_hi(v.w);
        }
        srcp = nxt;
    }

#pragma unroll
    for (int j = 0; j < 2; j++) {
        int c = lane + 32 * j;
        float dn = __shfl_sync(0xffffffffu, denom, c >> 3) + 1e-16f;
        float inv = 1.f / dn;
        float4 v0, v1;
        v0.x = acc[j][0] * inv; v0.y = acc[j][1] * inv;
        v0.z = acc[j][2] * inv; v0.w = acc[j][3] * inv;
        v1.x = acc[j][4] * inv; v1.y = acc[j][5] * inv;
        v1.z = acc[j][6] * inv; v1.w = acc[j][7] * inv;
        if (do_elu) {
            v0.x = rna_tf32(eluf(v0.x)); v0.y = rna_tf32(eluf(v0.y));
            v0.z = rna_tf32(eluf(v0.z)); v0.w = rna_tf32(eluf(v0.w));
            v1.x = rna_tf32(eluf(v1.x)); v1.y = rna_tf32(eluf(v1.y));
            v1.z = rna_tf32(eluf(v1.z)); v1.w = rna_tf32(eluf(v1.w));
        }
        float4* ob = (float4*)(out + (size_t)node * 512 + c * 8);
        ob[0] = v0;
        ob[1] = v1;
    }
}

// ---------------- small prep kernels ----------------
__global__ void round_tf32_k(float* __restrict__ dst, const float* __restrict__ src, int n) {
    int i = blockIdx.x * blockDim.x + threadIdx.x;
    if (i < n) dst[i] = rna_tf32(src[i]);
}
__global__ void transpose_round(float* __restrict__ Wt, const float* __restrict__ W) {
    int i = blockIdx.x * blockDim.x + threadIdx.x;
    if (i >= 256 * 128) return;
    int n = i >> 7, k = i & 127;
    Wt[i] = rna_tf32(W[k * 256 + n]);
}
__global__ void repack_round(float* __restrict__ Bt, const float* __restrict__ w, int fin) {
    int i = blockIdx.x * blockDim.x + threadIdx.x;
    if (i >= fin * 512) return;
    int n = i / fin, k = i % fin;
    int h = n >> 6, o = n & 63;
    Bt[i] = rna_tf32(w[((size_t)(h * fin + k) << 6) + o]);
}

__global__ void fa_kernel(const float* __restrict__ trans1, const float* __restrict__ aw1) {
    int o = threadIdx.x;
    float acc = 0.f;
    for (int f = 0; f < FUNI; f++) acc += trans1[f] * aw1[f * 64 + o];
    g_fa[o] = acc;
}

__global__ __launch_bounds__(64) void final_kernel(const float* __restrict__ aw2,
                                                   const float* __restrict__ am,
                                                   const float* __restrict__ fcw,
                                                   const float* __restrict__ fcb,
                                                   float* __restrict__ out) {
    __shared__ float ta[2][64];
    __shared__ float r0[64], r1[64];
    __shared__ float sc[2];
    int n = blockIdx.x, o = threadIdx.x;

    float m0 = 0.f, m1 = 0.f;
    const float* p0 = g_o1a + (size_t)n * 512 + o;
    const float* p1 = g_o1b + (size_t)n * 512 + o;
#pragma unroll
    for (int h = 0; h < 8; h++) { m0 += p0[h * 64]; m1 += p1[h * 64]; }
    m0 *= 0.125f; m1 *= 0.125f;
    ta[0][o] = m0; ta[1][o] = m1;
    __syncthreads();

    float amo = am[o];
    float fa = g_fa[o];
    {
        float acc0 = fa, acc1 = fa;
        for (int d = 0; d < 64; d++) {
            float w = aw2[d * 64 + o];
            acc0 += ta[0][d] * w;
            acc1 += ta[1][d] * w;
        }
        r0[o] = tanhf(acc0) * amo;
        r1[o] = tanhf(acc1) * amo;
    }
    __syncthreads();
    if (o == 0) {
        float s0 = 0.f, s1 = 0.f;
        for (int d = 0; d < 64; d++) { s0 += r0[d]; s1 += r1[d]; }
        sc[0] = s0; sc[1] = s1;
    }
    __syncthreads();
    float mx = fmaxf(sc[0], sc[1]);
    float b0 = __expf(sc[0] - mx), b1 = __expf(sc[1] - mx);
    float inv = 1.f / (b0 + b1);
    b0 *= inv; b1 *= inv;
    float fus = b0 * m0 + b1 * m1;

    r0[o] = m0 * fcw[o * 2 + 0] + m1 * fcw[(64 + o) * 2 + 0] + fus * fcw[(128 + o) * 2 + 0];
    r1[o] = m0 * fcw[o * 2 + 1] + m1 * fcw[(64 + o) * 2 + 1] + fus * fcw[(128 + o) * 2 + 1];
    __syncthreads();
    if (o == 0) {
        float l0 = fcb[0], l1 = fcb[1];
        for (int d = 0; d < 64; d++) { l0 += r0[d]; l1 += r1[d]; }
        float m = fmaxf(l0, l1);
        float lse = m + logf(__expf(l0 - m) + __expf(l1 - m));
        out[n * 2 + 0] = l0 - lse;
        out[n * 2 + 1] = l1 - lse;
    }
}

// ---------------- launcher ----------------
extern "C" void kernel_launch(void* const* d_in, const int* in_sizes, int n_in,
                              void* d_out, int out_size)
{
    const float* hemb0 = (const float*)d_in[0];
    const float* hemb1 = (const float*)d_in[1];
    const float* W0    = (const float*)d_in[2];
    const float* W1    = (const float*)d_in[3];
    const float* gw[2][2]    = {{(const float*)d_in[4],  (const float*)d_in[7]},
                                {(const float*)d_in[10], (const float*)d_in[13]}};
    const float* gasrc[2][2] = {{(const float*)d_in[5],  (const float*)d_in[8]},
                                {(const float*)d_in[11], (const float*)d_in[14]}};
    const float* gatrg[2][2] = {{(const float*)d_in[6],  (const float*)d_in[9]},
                                {(const float*)d_in[12], (const float*)d_in[15]}};
    const float* aw1 = (const float*)d_in[16];
    const float* aw2 = (const float*)d_in[17];
    const float* am  = (const float*)d_in[18];
    const float* fcw = (const float*)d_in[19];
    const float* fcb = (const float*)d_in[20];
    const int* edge[2] = {(const int*)d_in[21], (const int*)d_in[22]};

    float *trans[2], *Bp, *hp, *x0, *o1[2], *tmp0;
    uint32_t* hpb;
    int *csr[2], *rowptr[2];
    cudaGetSymbolAddress((void**)&trans[0], g_trans0);
    cudaGetSymbolAddress((void**)&trans[1], g_trans1);
    cudaGetSymbolAddress((void**)&Bp,  g_Bp);
    cudaGetSymbolAddress((void**)&hp,  g_hp);
    cudaGetSymbolAddress((void**)&hpb, g_hpb);
    cudaGetSymbolAddress((void**)&x0,  g_x0);
    cudaGetSymbolAddress((void**)&o1[0], g_o1a);
    cudaGetSymbolAddress((void**)&o1[1], g_o1b);
    cudaGetSymbolAddress((void**)&tmp0, g_tmp0);
    {
        int* base;
        cudaGetSymbolAddress((void**)&base, g_csr);
        csr[0] = base; csr[1] = base + EE;
        cudaGetSymbolAddress((void**)&base, g_rowptr);
        rowptr[0] = base; rowptr[1] = base + (NN + 1);
    }

    cudaFuncSetAttribute(gemm_mma, cudaFuncAttributeMaxDynamicSharedMemorySize, SMEM_GEMM);

    const dim3 gridT(FUNI / 128, (NN + 127) / 128);
    const dim3 gridH(HF / 128,  (NN + 127) / 128);

    // CSR build (per type; reused by both layers)
    for (int t = 0; t < 2; t++) {
        const int* src = edge[t];
        const int* trg = edge[t] + EE;
        zero_cnt<<<(NN + 255) / 256, 256>>>();
        hist_kernel<<<(EE + 255) / 256, 256>>>(trg);
        scan_kernel<<<1, 1024>>>(t);
        fill_kernel<<<(EE + 255) / 256, 256>>>(src, trg, t);
    }

    // round hemb inputs to tf32
    round_tf32_k<<<(NN * 128 + 255) / 256, 256>>>(tmp0, hemb0, NN * 128);
    round_tf32_k<<<(NN * 128 + 255) / 256, 256>>>(hp,   hemb1, NN * 128);

    // trans GEMMs (round outputs: they feed layer-0 GEMM A)
    transpose_round<<<(256 * 128 + 255) / 256, 256>>>(Bp, W0);
    gemm_mma<<<gridT, 256, SMEM_GEMM>>>(tmp0, Bp, trans[0], NN, 128, FUNI, 1);
    transpose_round<<<(256 * 128 + 255) / 256, 256>>>(Bp, W1);
    gemm_mma<<<gridT, 256, SMEM_GEMM>>>(hp, Bp, trans[1], NN, 128, FUNI, 1);

    for (int t = 0; t < 2; t++) {
        // ---- layer 0 (fin = 256); ELU+round fused into gather ----
        repack_round<<<(FUNI * 512 + 255) / 256, 256>>>(Bp, gw[t][0], FUNI);
        gemm_mma<<<gridH, 256, SMEM_GEMM>>>(trans[t], Bp, hp, NN, FUNI, HF, 0);
        st_kernel<<<(NN * HH + 255) / 256, 256>>>(hp, gasrc[t][0], gatrg[t][0]);
        gather_agg<<<(NN * 32 + 255) / 256, 256>>>(csr[t], rowptr[t], hpb, x0, 1);

        // ---- layer 1 (fin = 512) ----
        repack_round<<<(HF * 512 + 255) / 256, 256>>>(Bp, gw[t][1], HF);
        gemm_mma<<<gridH, 256, SMEM_GEMM>>>(x0, Bp, hp, NN, HF, HF, 0);
        st_kernel<<<(NN * HH + 255) / 256, 256>>>(hp, gasrc[t][1], gatrg[t][1]);
        gather_agg<<<(NN * 32 + 255) / 256, 256>>>(csr[t], rowptr[t], hpb, o1[t], 0);
    }

    fa_kernel<<<1, 64>>>(trans[1], aw1);
    final_kernel<<<NN, 64>>>(aw2, am, fcw, fcb, (float*)d_out);
}